// round 8
// baseline (speedup 1.0000x reference)
#include <cuda_runtime.h>

// Problem constants (from reference: B=128, H=W=256, 68 keypoints)
#define HDIM 256
#define WDIM 256
#define HWSZ (HDIM * WDIM)          // 65536
#define NKPT 68
#define OFFSET_SCALE 6.0f
#define MAX_B 256

// Per-batch transform params: [b*12 + j*3 + i] = Rout[j][i], [b*12 + 9 + j] = T[j]
__device__ float g_params[MAX_B * 12];

// Y = inverse(X)^T for row-major 3x3 X. (inv^T = cofactor/det)
__device__ __forceinline__ void inv3_transpose(const float X[9], float Y[9]) {
    float c00 = X[4]*X[8] - X[5]*X[7];
    float c01 = X[5]*X[6] - X[3]*X[8];
    float c02 = X[3]*X[7] - X[4]*X[6];
    float c10 = X[2]*X[7] - X[1]*X[8];
    float c11 = X[0]*X[8] - X[2]*X[6];
    float c12 = X[1]*X[6] - X[0]*X[7];
    float c20 = X[1]*X[5] - X[2]*X[4];
    float c21 = X[2]*X[3] - X[0]*X[5];
    float c22 = X[0]*X[4] - X[1]*X[3];
    float det = X[0]*c00 + X[1]*c01 + X[2]*c02;
    float id  = 1.0f / det;
    Y[0] = c00*id; Y[1] = c01*id; Y[2] = c02*id;
    Y[3] = c10*id; Y[4] = c11*id; Y[5] = c12*id;
    Y[6] = c20*id; Y[7] = c21*id; Y[8] = c22*id;
}

// Kernel 1: one block per batch. Gather 68 keypoints, solve similarity transform.
// R (rotation part) = orthogonal polar factor of H^T, via scaled Newton iteration.
// uv may be int32 or int64 (JAX x64-dependent); detect at runtime.
__global__ void tform_kernel(const float* __restrict__ Offset,
                             const float* __restrict__ Posmap,
                             const float* __restrict__ meanp,
                             const int* __restrict__ uv32)
{
    const int b = blockIdx.x;
    __shared__ float src[NKPT][3];
    __shared__ float dst[NKPT][3];
    __shared__ int s_is64;

    // dtype sniff: if int64 (little-endian), the first 2*NKPT ints are
    // [lo,hi,lo,hi,...] with hi==0 always (values in [0,256)). If int32,
    // odd slots are random column coords — all-zero has prob ~256^-67.
    if (threadIdx.x == 0) {
        int any_odd = 0;
        #pragma unroll 4
        for (int i = 1; i < 2 * NKPT; i += 2) any_odd |= uv32[i];
        s_is64 = (any_odd == 0) ? 1 : 0;
    }
    __syncthreads();
    const int is64 = s_is64;

    const int k = threadIdx.x;
    if (k < NKPT) {
        int u, v;
        if (is64) { u = uv32[4*k]; v = uv32[4*k + 2]; }
        else      { u = uv32[2*k]; v = uv32[2*k + 1]; }
        int idx = u * WDIM + v;
        const size_t base = (size_t)b * 3 * HWSZ;
        #pragma unroll
        for (int c = 0; c < 3; ++c) {
            float d = Posmap[base + (size_t)c * HWSZ + idx];
            float o = Offset[base + (size_t)c * HWSZ + idx];
            float m = meanp[(size_t)c * HWSZ + idx];
            dst[k][c] = d;
            src[k][c] = fmaf(OFFSET_SCALE, o, m);
        }
    }
    __syncthreads();

    if (threadIdx.x != 0) return;

    // sd1 / sd2: sum of distances to keypoint 33
    float rx = src[33][0], ry = src[33][1], rz = src[33][2];
    float qx = dst[33][0], qy = dst[33][1], qz = dst[33][2];
    float s1 = 0.f, s2 = 0.f;
    for (int i = 0; i < NKPT; ++i) {
        float dx = src[i][0]-rx, dy = src[i][1]-ry, dz = src[i][2]-rz;
        s1 += sqrtf(dx*dx + dy*dy + dz*dz);
        float ex = dst[i][0]-qx, ey = dst[i][1]-qy, ez = dst[i][2]-qz;
        s2 += sqrtf(ex*ex + ey*ey + ez*ez);
    }
    const float s = s2 / s1;

    // Means of A = src*s and B = dst
    float mA0=0,mA1=0,mA2=0, mB0=0,mB1=0,mB2=0;
    for (int i = 0; i < NKPT; ++i) {
        mA0 += src[i][0]; mA1 += src[i][1]; mA2 += src[i][2];
        mB0 += dst[i][0]; mB1 += dst[i][1]; mB2 += dst[i][2];
    }
    const float inv_n = 1.0f / (float)NKPT;
    mA0 *= s * inv_n; mA1 *= s * inv_n; mA2 *= s * inv_n;
    mB0 *= inv_n; mB1 *= inv_n; mB2 *= inv_n;

    // H[i][j] = sum_k (A[k][i]-mA[i]) * (B[k][j]-mB[j])
    float Hm[9] = {0,0,0,0,0,0,0,0,0};
    for (int kk = 0; kk < NKPT; ++kk) {
        float a0 = fmaf(s, src[kk][0], -mA0);
        float a1 = fmaf(s, src[kk][1], -mA1);
        float a2 = fmaf(s, src[kk][2], -mA2);
        float b0 = dst[kk][0] - mB0;
        float b1 = dst[kk][1] - mB1;
        float b2 = dst[kk][2] - mB2;
        Hm[0] = fmaf(a0, b0, Hm[0]); Hm[1] = fmaf(a0, b1, Hm[1]); Hm[2] = fmaf(a0, b2, Hm[2]);
        Hm[3] = fmaf(a1, b0, Hm[3]); Hm[4] = fmaf(a1, b1, Hm[4]); Hm[5] = fmaf(a1, b2, Hm[5]);
        Hm[6] = fmaf(a2, b0, Hm[6]); Hm[7] = fmaf(a2, b1, Hm[7]); Hm[8] = fmaf(a2, b2, Hm[8]);
    }

    // Reference R = V U^T with H = U S Vh  ==  polar factor of H^T.
    // Scaled Newton: X <- 0.5*(g*X + (1/g)*X^-T), quadratic convergence,
    // preserves det sign (handles the reflection case identically to V U^T).
    float X[9];
    X[0]=Hm[0]; X[1]=Hm[3]; X[2]=Hm[6];
    X[3]=Hm[1]; X[4]=Hm[4]; X[5]=Hm[7];
    X[6]=Hm[2]; X[7]=Hm[5]; X[8]=Hm[8];

    float Y[9];
    for (int it = 0; it < 30; ++it) {
        inv3_transpose(X, Y);
        float nx = 0.f, ny = 0.f;
        #pragma unroll
        for (int i = 0; i < 9; ++i) { nx += X[i]*X[i]; ny += Y[i]*Y[i]; }
        float g  = sqrtf(sqrtf(ny / nx));
        float ig = 1.0f / g;
        float diff = 0.f;
        #pragma unroll
        for (int i = 0; i < 9; ++i) {
            float xn = 0.5f * (g * X[i] + ig * Y[i]);
            float d  = xn - X[i];
            diff += d * d;
            X[i] = xn;
        }
        if (diff <= 1e-14f * nx) break;
    }

    // X = R row-major: R[j][i] = X[j*3+i].
    // t[j] = mB[j] - sum_i mA[i] * R[j][i]   (mA carries s; R unscaled here)
    float t0 = mB0 - (mA0*X[0] + mA1*X[1] + mA2*X[2]);
    float t1 = mB1 - (mA0*X[3] + mA1*X[4] + mA2*X[5]);
    float t2 = mB2 - (mA0*X[6] + mA1*X[7] + mA2*X[8]);

    float* p = &g_params[b * 12];
    #pragma unroll
    for (int i = 0; i < 9; ++i) p[i] = X[i] * s;   // scaled R, row-major [j][i]
    p[9] = t0; p[10] = t1; p[11] = t2;
}

// Kernel 2: streaming affine apply. 64 blocks per batch, 256 threads, float4/thread.
// out[b][j][pix] = sum_i Rout[j][i] * (6*Offset[b][i][pix] + mean[i][pix]) + T[j]
// Cache policy: Offset streamed (ldcs), out streamed (stcs), mean kept L2-resident.
__global__ void __launch_bounds__(256) apply_kernel(const float4* __restrict__ Offset,
                                                    const float4* __restrict__ meanp,
                                                    float4* __restrict__ out)
{
    const int b = blockIdx.x >> 6;
    const int p = ((blockIdx.x & 63) << 8) | threadIdx.x;   // 0..16383 (HW/4)
    const int plane = HWSZ / 4;                              // 16384

    // Warp-uniform param loads (single transaction, L1/L2-hit after block 0).
    const float* gp = &g_params[b * 12];
    const float R00 = __ldg(gp+0), R01 = __ldg(gp+1),  R02 = __ldg(gp+2);
    const float R10 = __ldg(gp+3), R11 = __ldg(gp+4),  R12 = __ldg(gp+5);
    const float R20 = __ldg(gp+6), R21 = __ldg(gp+7),  R22 = __ldg(gp+8);
    const float T0  = __ldg(gp+9), T1  = __ldg(gp+10), T2  = __ldg(gp+11);

    const float4* ob = Offset + (size_t)b * 3 * plane;
    float4 x = __ldcs(ob + p);                 // single-use stream: evict-first
    float4 y = __ldcs(ob + p + plane);
    float4 z = __ldcs(ob + p + 2 * plane);
    float4 mx = __ldg(meanp + p);              // reused by all batches: keep cached
    float4 my = __ldg(meanp + p + plane);
    float4 mz = __ldg(meanp + p + 2 * plane);

    float o0[4], o1[4], o2[4];
    o0[0]=fmaf(OFFSET_SCALE,x.x,mx.x); o0[1]=fmaf(OFFSET_SCALE,x.y,mx.y);
    o0[2]=fmaf(OFFSET_SCALE,x.z,mx.z); o0[3]=fmaf(OFFSET_SCALE,x.w,mx.w);
    o1[0]=fmaf(OFFSET_SCALE,y.x,my.x); o1[1]=fmaf(OFFSET_SCALE,y.y,my.y);
    o1[2]=fmaf(OFFSET_SCALE,y.z,my.z); o1[3]=fmaf(OFFSET_SCALE,y.w,my.w);
    o2[0]=fmaf(OFFSET_SCALE,z.x,mz.x); o2[1]=fmaf(OFFSET_SCALE,z.y,mz.y);
    o2[2]=fmaf(OFFSET_SCALE,z.z,mz.z); o2[3]=fmaf(OFFSET_SCALE,z.w,mz.w);

    float4 r0, r1, r2;
    float* pr0 = &r0.x; float* pr1 = &r1.x; float* pr2 = &r2.x;
    #pragma unroll
    for (int l = 0; l < 4; ++l) {
        pr0[l] = fmaf(R00, o0[l], fmaf(R01, o1[l], fmaf(R02, o2[l], T0)));
        pr1[l] = fmaf(R10, o0[l], fmaf(R11, o1[l], fmaf(R12, o2[l], T1)));
        pr2[l] = fmaf(R20, o0[l], fmaf(R21, o1[l], fmaf(R22, o2[l], T2)));
    }

    float4* outb = out + (size_t)b * 3 * plane;
    __stcs(outb + p,             r0);          // write-once: streaming store
    __stcs(outb + p + plane,     r1);
    __stcs(outb + p + 2 * plane, r2);
}

extern "C" void kernel_launch(void* const* d_in, const int* in_sizes, int n_in,
                              void* d_out, int out_size)
{
    const float* Offset = (const float*)d_in[0];
    const float* Posmap = (const float*)d_in[1];
    const float* meanp  = (const float*)d_in[2];
    const int*   uv     = (const int*)d_in[3];
    float* out = (float*)d_out;

    const int B = in_sizes[0] / (3 * HWSZ);

    tform_kernel<<<B, 96>>>(Offset, Posmap, meanp, uv);
    apply_kernel<<<B * 64, 256>>>((const float4*)Offset, (const float4*)meanp, (float4*)out);
}

// round 10
// speedup vs baseline: 1.1483x; 1.1483x over previous
#include <cuda_runtime.h>

// Problem constants (from reference: B=128, H=W=256, 68 keypoints)
#define HDIM 256
#define WDIM 256
#define HWSZ (HDIM * WDIM)          // 65536
#define NKPT 68
#define OFFSET_SCALE 6.0f
#define MAX_B 256

// Per-batch transform params: [b*12 + j*3 + i] = Rout[j][i], [b*12 + 9 + j] = T[j]
__device__ float g_params[MAX_B * 12];

// Y = inverse(X)^T for row-major 3x3 X. (inv^T = cofactor/det)
__device__ __forceinline__ void inv3_transpose(const float X[9], float Y[9]) {
    float c00 = X[4]*X[8] - X[5]*X[7];
    float c01 = X[5]*X[6] - X[3]*X[8];
    float c02 = X[3]*X[7] - X[4]*X[6];
    float c10 = X[2]*X[7] - X[1]*X[8];
    float c11 = X[0]*X[8] - X[2]*X[6];
    float c12 = X[1]*X[6] - X[0]*X[7];
    float c20 = X[1]*X[5] - X[2]*X[4];
    float c21 = X[2]*X[3] - X[0]*X[5];
    float c22 = X[0]*X[4] - X[1]*X[3];
    float det = X[0]*c00 + X[1]*c01 + X[2]*c02;
    float id  = 1.0f / det;
    Y[0] = c00*id; Y[1] = c01*id; Y[2] = c02*id;
    Y[3] = c10*id; Y[4] = c11*id; Y[5] = c12*id;
    Y[6] = c20*id; Y[7] = c21*id; Y[8] = c22*id;
}

__device__ __forceinline__ float warp_sum(float v) {
    #pragma unroll
    for (int off = 16; off > 0; off >>= 1)
        v += __shfl_xor_sync(0xFFFFFFFFu, v, off);
    return v;
}

// Kernel 1: one block (96 threads = 3 warps) per batch.
// Parallel reductions over 68 keypoints; only the 3x3 Newton polar stays serial.
__global__ void __launch_bounds__(96) tform_kernel(const float* __restrict__ Offset,
                                                   const float* __restrict__ Posmap,
                                                   const float* __restrict__ meanp,
                                                   const int* __restrict__ uv32)
{
    const int b = blockIdx.x;
    __shared__ float src[NKPT][3];
    __shared__ float dst[NKPT][3];
    __shared__ float red[3][9];        // per-warp partials (max 9 quantities/round)
    __shared__ float bc[8];            // broadcast: s, mA0..2, mB0..2
    __shared__ int s_is64;

    const int tid  = threadIdx.x;
    const int wid  = tid >> 5;
    const int lane = tid & 31;

    // dtype sniff: int64 little-endian => all odd 32-bit words zero (values < 256).
    if (tid == 0) {
        int any_odd = 0;
        #pragma unroll 4
        for (int i = 1; i < 2 * NKPT; i += 2) any_odd |= uv32[i];
        s_is64 = (any_odd == 0) ? 1 : 0;
    }
    __syncthreads();
    const int is64 = s_is64;

    const int k = tid;
    const bool valid = (k < NKPT);
    if (valid) {
        int u, v;
        if (is64) { u = uv32[4*k]; v = uv32[4*k + 2]; }
        else      { u = uv32[2*k]; v = uv32[2*k + 1]; }
        int idx = u * WDIM + v;
        const size_t base = (size_t)b * 3 * HWSZ;
        #pragma unroll
        for (int c = 0; c < 3; ++c) {
            float d = Posmap[base + (size_t)c * HWSZ + idx];
            float o = Offset[base + (size_t)c * HWSZ + idx];
            float m = meanp[(size_t)c * HWSZ + idx];
            dst[k][c] = d;
            src[k][c] = fmaf(OFFSET_SCALE, o, m);
        }
    }
    __syncthreads();

    // Round 1: reduce {d1, d2, sum(src xyz), sum(dst xyz)} = 8 quantities.
    {
        float v[8] = {0,0,0,0,0,0,0,0};
        if (valid) {
            float rx = src[33][0], ry = src[33][1], rz = src[33][2];
            float qx = dst[33][0], qy = dst[33][1], qz = dst[33][2];
            float dx = src[k][0]-rx, dy = src[k][1]-ry, dz = src[k][2]-rz;
            float ex = dst[k][0]-qx, ey = dst[k][1]-qy, ez = dst[k][2]-qz;
            v[0] = sqrtf(dx*dx + dy*dy + dz*dz);
            v[1] = sqrtf(ex*ex + ey*ey + ez*ez);
            v[2] = src[k][0]; v[3] = src[k][1]; v[4] = src[k][2];
            v[5] = dst[k][0]; v[6] = dst[k][1]; v[7] = dst[k][2];
        }
        #pragma unroll
        for (int q = 0; q < 8; ++q) v[q] = warp_sum(v[q]);
        if (lane == 0) {
            #pragma unroll
            for (int q = 0; q < 8; ++q) red[wid][q] = v[q];
        }
    }
    __syncthreads();
    if (tid == 0) {
        float t[8];
        #pragma unroll
        for (int q = 0; q < 8; ++q) t[q] = red[0][q] + red[1][q] + red[2][q];
        const float s = t[1] / t[0];
        const float inv_n = 1.0f / (float)NKPT;
        bc[0] = s;
        bc[1] = t[2] * s * inv_n;  bc[2] = t[3] * s * inv_n;  bc[3] = t[4] * s * inv_n;
        bc[4] = t[5] * inv_n;      bc[5] = t[6] * inv_n;      bc[6] = t[7] * inv_n;
    }
    __syncthreads();

    // Round 2: H[i][j] = sum_k (s*src[k][i]-mA[i]) * (dst[k][j]-mB[j]) — 9 quantities.
    {
        const float s = bc[0];
        const float mA0 = bc[1], mA1 = bc[2], mA2 = bc[3];
        const float mB0 = bc[4], mB1 = bc[5], mB2 = bc[6];
        float h[9] = {0,0,0,0,0,0,0,0,0};
        if (valid) {
            float a0 = fmaf(s, src[k][0], -mA0);
            float a1 = fmaf(s, src[k][1], -mA1);
            float a2 = fmaf(s, src[k][2], -mA2);
            float b0 = dst[k][0] - mB0;
            float b1 = dst[k][1] - mB1;
            float b2 = dst[k][2] - mB2;
            h[0] = a0*b0; h[1] = a0*b1; h[2] = a0*b2;
            h[3] = a1*b0; h[4] = a1*b1; h[5] = a1*b2;
            h[6] = a2*b0; h[7] = a2*b1; h[8] = a2*b2;
        }
        #pragma unroll
        for (int q = 0; q < 9; ++q) h[q] = warp_sum(h[q]);
        if (lane == 0) {
            #pragma unroll
            for (int q = 0; q < 9; ++q) red[wid][q] = h[q];
        }
    }
    __syncthreads();

    if (tid != 0) return;

    float Hm[9];
    #pragma unroll
    for (int q = 0; q < 9; ++q) Hm[q] = red[0][q] + red[1][q] + red[2][q];

    const float s   = bc[0];
    const float mA0 = bc[1], mA1 = bc[2], mA2 = bc[3];
    const float mB0 = bc[4], mB1 = bc[5], mB2 = bc[6];

    // Reference R = V U^T (H = U S Vh) == polar factor of H^T.
    // Scaled Newton: X <- 0.5*(g*X + (1/g)*X^-T); det-sign preserving.
    float X[9];
    X[0]=Hm[0]; X[1]=Hm[3]; X[2]=Hm[6];
    X[3]=Hm[1]; X[4]=Hm[4]; X[5]=Hm[7];
    X[6]=Hm[2]; X[7]=Hm[5]; X[8]=Hm[8];

    float Y[9];
    for (int it = 0; it < 30; ++it) {
        inv3_transpose(X, Y);
        float nx = 0.f, ny = 0.f;
        #pragma unroll
        for (int i = 0; i < 9; ++i) { nx += X[i]*X[i]; ny += Y[i]*Y[i]; }
        float g  = sqrtf(sqrtf(ny / nx));
        float ig = 1.0f / g;
        float diff = 0.f;
        #pragma unroll
        for (int i = 0; i < 9; ++i) {
            float xn = 0.5f * (g * X[i] + ig * Y[i]);
            float d  = xn - X[i];
            diff += d * d;
            X[i] = xn;
        }
        if (diff <= 1e-14f * nx) break;
    }

    // X = R row-major: R[j][i] = X[j*3+i];  t[j] = mB[j] - sum_i mA[i]*R[j][i]
    float t0 = mB0 - (mA0*X[0] + mA1*X[1] + mA2*X[2]);
    float t1 = mB1 - (mA0*X[3] + mA1*X[4] + mA2*X[5]);
    float t2 = mB2 - (mA0*X[6] + mA1*X[7] + mA2*X[8]);

    float* p = &g_params[b * 12];
    #pragma unroll
    for (int i = 0; i < 9; ++i) p[i] = X[i] * s;   // scaled R, row-major [j][i]
    p[9] = t0; p[10] = t1; p[11] = t2;
}

// Kernel 2: streaming affine apply, 2 float4-triples per thread (12 front-batched
// loads -> MLP_p1~12). 32 blocks per batch, 256 threads.
// out[b][j][pix] = sum_i Rout[j][i] * (6*Offset[b][i][pix] + mean[i][pix]) + T[j]
__global__ void __launch_bounds__(256) apply_kernel(const float4* __restrict__ Offset,
                                                    const float4* __restrict__ meanp,
                                                    float4* __restrict__ out)
{
    const int b     = blockIdx.x >> 5;
    const int chunk = blockIdx.x & 31;
    const int p0    = (chunk << 9) | threadIdx.x;   // chunk*512 + tid
    const int p1    = p0 + 256;
    const int plane = HWSZ / 4;                      // 16384

    // Warp-uniform param loads (single transaction, L2-hit after block 0).
    const float* gp = &g_params[b * 12];
    const float R00 = __ldg(gp+0), R01 = __ldg(gp+1),  R02 = __ldg(gp+2);
    const float R10 = __ldg(gp+3), R11 = __ldg(gp+4),  R12 = __ldg(gp+5);
    const float R20 = __ldg(gp+6), R21 = __ldg(gp+7),  R22 = __ldg(gp+8);
    const float T0  = __ldg(gp+9), T1  = __ldg(gp+10), T2  = __ldg(gp+11);

    const float4* ob = Offset + (size_t)b * 3 * plane;
    // Front-batch all 12 tile loads (6 streaming, 6 L2-resident).
    float4 x0 = __ldcs(ob + p0);
    float4 x1 = __ldcs(ob + p1);
    float4 y0 = __ldcs(ob + p0 + plane);
    float4 y1 = __ldcs(ob + p1 + plane);
    float4 z0 = __ldcs(ob + p0 + 2 * plane);
    float4 z1 = __ldcs(ob + p1 + 2 * plane);
    float4 mx0 = __ldg(meanp + p0);
    float4 mx1 = __ldg(meanp + p1);
    float4 my0 = __ldg(meanp + p0 + plane);
    float4 my1 = __ldg(meanp + p1 + plane);
    float4 mz0 = __ldg(meanp + p0 + 2 * plane);
    float4 mz1 = __ldg(meanp + p1 + 2 * plane);

    float4* outb = out + (size_t)b * 3 * plane;

    #pragma unroll
    for (int u = 0; u < 2; ++u) {
        const float4 xx = u ? x1 : x0, yy = u ? y1 : y0, zz = u ? z1 : z0;
        const float4 mx = u ? mx1 : mx0, my = u ? my1 : my0, mz = u ? mz1 : mz0;
        const int p = u ? p1 : p0;

        float o0[4], o1[4], o2[4];
        o0[0]=fmaf(OFFSET_SCALE,xx.x,mx.x); o0[1]=fmaf(OFFSET_SCALE,xx.y,mx.y);
        o0[2]=fmaf(OFFSET_SCALE,xx.z,mx.z); o0[3]=fmaf(OFFSET_SCALE,xx.w,mx.w);
        o1[0]=fmaf(OFFSET_SCALE,yy.x,my.x); o1[1]=fmaf(OFFSET_SCALE,yy.y,my.y);
        o1[2]=fmaf(OFFSET_SCALE,yy.z,my.z); o1[3]=fmaf(OFFSET_SCALE,yy.w,my.w);
        o2[0]=fmaf(OFFSET_SCALE,zz.x,mz.x); o2[1]=fmaf(OFFSET_SCALE,zz.y,mz.y);
        o2[2]=fmaf(OFFSET_SCALE,zz.z,mz.z); o2[3]=fmaf(OFFSET_SCALE,zz.w,mz.w);

        float4 r0, r1, r2;
        float* pr0 = &r0.x; float* pr1 = &r1.x; float* pr2 = &r2.x;
        #pragma unroll
        for (int l = 0; l < 4; ++l) {
            pr0[l] = fmaf(R00, o0[l], fmaf(R01, o1[l], fmaf(R02, o2[l], T0)));
            pr1[l] = fmaf(R10, o0[l], fmaf(R11, o1[l], fmaf(R12, o2[l], T1)));
            pr2[l] = fmaf(R20, o0[l], fmaf(R22 * 0.0f + R21, o1[l], fmaf(R22, o2[l], T2)));
        }

        __stcs(outb + p,             r0);
        __stcs(outb + p + plane,     r1);
        __stcs(outb + p + 2 * plane, r2);
    }
}

extern "C" void kernel_launch(void* const* d_in, const int* in_sizes, int n_in,
                              void* d_out, int out_size)
{
    const float* Offset = (const float*)d_in[0];
    const float* Posmap = (const float*)d_in[1];
    const float* meanp  = (const float*)d_in[2];
    const int*   uv     = (const int*)d_in[3];
    float* out = (float*)d_out;

    const int B = in_sizes[0] / (3 * HWSZ);

    tform_kernel<<<B, 96>>>(Offset, Posmap, meanp, uv);
    apply_kernel<<<B * 32, 256>>>((const float4*)Offset, (const float4*)meanp, (float4*)out);
}